// round 12
// baseline (speedup 1.0000x reference)
#include <cuda_runtime.h>

#define IMG_H 512
#define IMG_W 512
#define RPB   32
#define KRAD  15
#define INV_KK (1.0f/961.0f)
#define TPB   128
#define NW    4
#define FULL  0xffffffffu

__device__ double g_acc[3];
__device__ unsigned int g_count;

// Windowed 8-chunk box sum (linear in its 8 inputs).
__device__ __forceinline__ void window8(
    float a0, float a1, float a2, float a3,
    float b0, float b1, float b2, float b3,
    int lane, float wsv[4])
{
    float A01 = a0 + a1, A012 = A01 + a2;
    float Qown = A012 + a3;
    float B01 = b0 + b1, B012 = B01 + b2;
    float QB   = B012 + b3;

    float s = Qown;
    {
        float nb = __shfl_down_sync(FULL, s, 1);  if (lane + 1 < 32) s += nb;
        nb = __shfl_down_sync(FULL, s, 2);        if (lane + 2 < 32) s += nb;
        nb = __shfl_down_sync(FULL, s, 4);        if (lane + 4 < 32) s += nb;
    }
    float p = QB;
    {
        float nb = __shfl_up_sync(FULL, p, 1);  if (lane >= 1) p += nb;
        nb = __shfl_up_sync(FULL, p, 2);        if (lane >= 2) p += nb;
        nb = __shfl_up_sync(FULL, p, 4);        if (lane >= 4) p += nb;
    }
    float pbv = __shfl_sync(FULL, p, max(lane - 25, 0));
    float W8  = s + ((lane >= 25) ? pbv : 0.f);

    float fa0 = __shfl_sync(FULL, a0,   lane + 8);
    float fa1 = __shfl_sync(FULL, A01,  lane + 8);
    float fa2 = __shfl_sync(FULL, A012, lane + 8);
    float fb0 = __shfl_sync(FULL, b0,   max(lane - 24, 0));
    float fb1 = __shfl_sync(FULL, B01,  max(lane - 24, 0));
    float fb2 = __shfl_sync(FULL, B012, max(lane - 24, 0));
    float f0   = (lane < 24) ? fa0 : fb0;
    float f01  = (lane < 24) ? fa1 : fb1;
    float f012 = (lane < 24) ? fa2 : fb2;

    wsv[0] = W8 - a0;
    wsv[1] = W8 - A01  + f0;
    wsv[2] = W8 - A012 + f01;
    wsv[3] = W8 - Qown + f012;
}

__device__ __forceinline__ void accum_pixels(
    const float wsv[4], float4 xc, float4 tc,
    float& r0, float& r1, float& r2)
{
    float xv[4] = { xc.x, xc.y, xc.z, xc.w };
    float tv[4] = { tc.x, tc.y, tc.z, tc.w };
    #pragma unroll
    for (int j = 0; j < 4; ++j) {
        float x = xv[j], t = tv[j];
        float e   = __expf(-fabsf(x));
        float l1p = __logf(1.0f + e);
        float bce = l1p + fmaxf(x, 0.f) - t * x;
        float rp  = __fdividef(1.0f, 1.0f + e);
        float p_  = (x >= 0.f) ? rp : e * rp;
        float weit = 1.0f + 5.0f * fabsf(wsv[j] * INV_KK - t);
        r0 += weit * bce;
        r1 += p_ * t * weit;
        r2 += (p_ + t) * weit;
    }
}

// GUARDED = 1 for edge strips (row-bound checks), 0 for interior (no checks).
// X center loads software-pipelined one pair ahead.
#define MAIN_LOOP(GUARDED)                                                     \
  {                                                                            \
    float4 xc1 = __ldcs((const float4*)pX);                                    \
    float4 xc2 = __ldcs((const float4*)(pX + IMG_W));                          \
    _Pragma("unroll 1")                                                        \
    for (int r = 0; r < RPB; r += 2) {                                         \
        /* prefetch next pair's X (predicated; off at final iteration) */      \
        float4 nx1, nx2;                                                       \
        if (r + 2 < RPB) {                                                     \
            nx1 = __ldcs((const float4*)(pX + 2 * IMG_W));                     \
            nx2 = __ldcs((const float4*)(pX + 3 * IMG_W));                     \
        }                                                                      \
        float4 tc1 = *(const float4*)(pA - 15 * IMG_W + 16);                   \
        float4 tc2 = *(const float4*)(pA - 14 * IMG_W + 16);                   \
        const int y = y0 + r; (void)y;                                         \
        /* w = vs + add1 */                                                    \
        if (!GUARDED || (y + KRAD) < IMG_H) {                                  \
            if (validA) { float4 v = *(const float4*)pA;                       \
                va0 += v.x; va1 += v.y; va2 += v.z; va3 += v.w; }              \
            if (validB) { float4 v = *(const float4*)(pA + 128);               \
                vb0 += v.x; vb1 += v.y; vb2 += v.z; vb3 += v.w; }              \
        }                                                                      \
        /* delta = add2 - ret1 (independent of w) */                           \
        float da0 = 0.f, da1 = 0.f, da2 = 0.f, da3 = 0.f;                      \
        float db0 = 0.f, db1 = 0.f, db2 = 0.f, db3 = 0.f;                      \
        if (!GUARDED || (y + KRAD + 1) < IMG_H) {                              \
            if (validA) { float4 v = *(const float4*)(pA + IMG_W);             \
                da0 += v.x; da1 += v.y; da2 += v.z; da3 += v.w; }              \
            if (validB) { float4 v = *(const float4*)(pA + IMG_W + 128);       \
                db0 += v.x; db1 += v.y; db2 += v.z; db3 += v.w; }              \
        }                                                                      \
        if (!GUARDED || (y - KRAD) >= 0) {                                     \
            if (validA) { float4 v = *(const float4*)(pA - 30 * IMG_W);        \
                da0 -= v.x; da1 -= v.y; da2 -= v.z; da3 -= v.w; }              \
            if (validB) { float4 v = *(const float4*)(pA - 30 * IMG_W + 128);  \
                db0 -= v.x; db1 -= v.y; db2 -= v.z; db3 -= v.w; }              \
        }                                                                      \
        /* two independent scan chains */                                      \
        float wsv1[4], wsvd[4];                                                \
        window8(va0,va1,va2,va3, vb0,vb1,vb2,vb3, lane, wsv1);                 \
        window8(da0,da1,da2,da3, db0,db1,db2,db3, lane, wsvd);                 \
        float wsv2[4] = { wsv1[0]+wsvd[0], wsv1[1]+wsvd[1],                    \
                          wsv1[2]+wsvd[2], wsv1[3]+wsvd[3] };                  \
        accum_pixels(wsv1, xc1, tc1, r0, r1, r2);                              \
        accum_pixels(wsv2, xc2, tc2, r0, r1, r2);                              \
        /* fold ret2 into delta; advance basis */                              \
        if (!GUARDED || (y - KRAD + 1) >= 0) {                                 \
            if (validA) { float4 v = *(const float4*)(pA - 29 * IMG_W);        \
                da0 -= v.x; da1 -= v.y; da2 -= v.z; da3 -= v.w; }              \
            if (validB) { float4 v = *(const float4*)(pA - 29 * IMG_W + 128);  \
                db0 -= v.x; db1 -= v.y; db2 -= v.z; db3 -= v.w; }              \
        }                                                                      \
        va0 += da0; va1 += da1; va2 += da2; va3 += da3;                        \
        vb0 += db0; vb1 += db1; vb2 += db2; vb3 += db3;                        \
        xc1 = nx1; xc2 = nx2;                                                  \
        pA += 2 * IMG_W; pX += 2 * IMG_W;                                      \
    }                                                                          \
  }

__global__ __launch_bounds__(TPB, 7) void wiou_bce_main(
    const float* __restrict__ X,   // logits
    const float* __restrict__ T,   // targets
    float* __restrict__ out, int nblocks, double inv_count)
{
    __shared__ float red[NW][3];

    const int tid  = threadIdx.x;
    const int lane = tid & 31;
    const int w    = tid >> 5;

    const int bpi = IMG_H / RPB;            // 16 strips per image
    const int n   = blockIdx.x / bpi;
    const int y0  = (blockIdx.x % bpi) * RPB;

    const float* Tn = T + (size_t)n * IMG_H * IMG_W;
    const float* Xn = X + (size_t)n * IMG_H * IMG_W;

    const int colA = w * 128 - 16 + lane * 4;
    const bool validA = !(w == 0 && lane < 4);
    const bool validB = (lane < 8) && !(w == 3 && lane >= 4);

    float va0 = 0.f, va1 = 0.f, va2 = 0.f, va3 = 0.f;
    float vb0 = 0.f, vb1 = 0.f, vb2 = 0.f, vb3 = 0.f;

    // ---- prologue: rows [y0-15, y0+14] ----
    {
        int klo = (y0 - KRAD < 0) ? 0 : (y0 - KRAD);
        const float* row = Tn + (ptrdiff_t)klo * IMG_W + colA;
        for (int yy = klo; yy <= y0 + KRAD - 1; ++yy) {
            if (validA) { float4 v = *(const float4*)row;
                va0 += v.x; va1 += v.y; va2 += v.z; va3 += v.w; }
            if (validB) { float4 v = *(const float4*)(row + 128);
                vb0 += v.x; vb1 += v.y; vb2 += v.z; vb3 += v.w; }
            row += IMG_W;
        }
    }

    float r0 = 0.f, r1 = 0.f, r2 = 0.f;

    const float* pA = Tn + (ptrdiff_t)(y0 + KRAD) * IMG_W + colA;
    const float* pX = Xn + (ptrdiff_t)y0 * IMG_W + (colA + 16);

    // interior strips: all row guards constant-true
    if (y0 >= KRAD + 1 && y0 + RPB - 1 + 1 + KRAD < IMG_H) {
        MAIN_LOOP(0)
    } else {
        MAIN_LOOP(1)
    }

    // ---- block reduction ----
    #pragma unroll
    for (int off = 16; off > 0; off >>= 1) {
        r0 += __shfl_down_sync(FULL, r0, off);
        r1 += __shfl_down_sync(FULL, r1, off);
        r2 += __shfl_down_sync(FULL, r2, off);
    }
    if (lane == 0) { red[w][0] = r0; red[w][1] = r1; red[w][2] = r2; }
    __syncthreads();

    if (tid == 0) {
        float s0 = red[0][0] + red[1][0] + red[2][0] + red[3][0];
        float s1 = red[0][1] + red[1][1] + red[2][1] + red[3][1];
        float s2 = red[0][2] + red[1][2] + red[2][2] + red[3][2];
        atomicAdd(&g_acc[0], (double)s0);
        atomicAdd(&g_acc[1], (double)s1);
        atomicAdd(&g_acc[2], (double)s2);
        __threadfence();
        unsigned int old = atomicAdd(&g_count, 1u);
        if (old == (unsigned int)(nblocks - 1)) {
            __threadfence();
            double d0 = g_acc[0], d1 = g_acc[1], d2 = g_acc[2];
            double wbce = d0 * inv_count;
            double uni  = d2 - d1;
            double wiou = 1.0 - (d1 + 1.0) / (uni + 1.0);
            out[0] = (float)(wbce + wiou);
            g_acc[0] = 0.0; g_acc[1] = 0.0; g_acc[2] = 0.0;
            g_count = 0u;
        }
    }
}

extern "C" void kernel_launch(void* const* d_in, const int* in_sizes, int n_in,
                              void* d_out, int out_size) {
    const float* X = (const float*)d_in[0];
    const float* T = (const float*)d_in[1];
    float* out = (float*)d_out;

    const int n_elem = in_sizes[0];
    const int imgs   = n_elem / (IMG_H * IMG_W);
    const int nb     = imgs * (IMG_H / RPB);

    wiou_bce_main<<<nb, TPB>>>(X, T, out, nb, 1.0 / (double)n_elem);
}

// round 13
// speedup vs baseline: 1.0642x; 1.0642x over previous
#include <cuda_runtime.h>

#define IMG_H 512
#define IMG_W 512
#define RPB   32
#define KRAD  15
#define INV_KK (1.0f/961.0f)
#define TPB   128
#define NW    4
#define FULL  0xffffffffu

__device__ double g_acc[3];
__device__ unsigned int g_count;

// packed f32x2 helpers (sm_100+; ptxas never emits these from C++)
#define ADDX2(d, s)   asm("add.rn.f32x2 %0, %0, %1;" : "+l"(d) : "l"(s))
#define FMANEG(d, s, n) asm("fma.rn.f32x2 %0, %1, %2, %0;" : "+l"(d) : "l"(s), "l"(n))
#define UNPX2(lo, hi, v) asm("mov.b64 {%0, %1}, %2;" : "=f"(lo), "=f"(hi) : "l"(v))

// Windowed 8-chunk box sum (linear in its 8 inputs).
__device__ __forceinline__ void window8(
    float a0, float a1, float a2, float a3,
    float b0, float b1, float b2, float b3,
    int lane, float wsv[4])
{
    float A01 = a0 + a1, A012 = A01 + a2;
    float Qown = A012 + a3;
    float B01 = b0 + b1, B012 = B01 + b2;
    float QB   = B012 + b3;

    float s = Qown;
    {
        float nb = __shfl_down_sync(FULL, s, 1);  if (lane + 1 < 32) s += nb;
        nb = __shfl_down_sync(FULL, s, 2);        if (lane + 2 < 32) s += nb;
        nb = __shfl_down_sync(FULL, s, 4);        if (lane + 4 < 32) s += nb;
    }
    float p = QB;
    {
        float nb = __shfl_up_sync(FULL, p, 1);  if (lane >= 1) p += nb;
        nb = __shfl_up_sync(FULL, p, 2);        if (lane >= 2) p += nb;
        nb = __shfl_up_sync(FULL, p, 4);        if (lane >= 4) p += nb;
    }
    float pbv = __shfl_sync(FULL, p, max(lane - 25, 0));
    float W8  = s + ((lane >= 25) ? pbv : 0.f);

    float fa0 = __shfl_sync(FULL, a0,   lane + 8);
    float fa1 = __shfl_sync(FULL, A01,  lane + 8);
    float fa2 = __shfl_sync(FULL, A012, lane + 8);
    float fb0 = __shfl_sync(FULL, b0,   max(lane - 24, 0));
    float fb1 = __shfl_sync(FULL, B01,  max(lane - 24, 0));
    float fb2 = __shfl_sync(FULL, B012, max(lane - 24, 0));
    float f0   = (lane < 24) ? fa0 : fb0;
    float f01  = (lane < 24) ? fa1 : fb1;
    float f012 = (lane < 24) ? fa2 : fb2;

    wsv[0] = W8 - a0;
    wsv[1] = W8 - A01  + f0;
    wsv[2] = W8 - A012 + f01;
    wsv[3] = W8 - Qown + f012;
}

__device__ __forceinline__ void accum_pixels(
    const float wsv[4], float4 xc, float4 tc,
    float& r0, float& r1, float& r2)
{
    float xv[4] = { xc.x, xc.y, xc.z, xc.w };
    float tv[4] = { tc.x, tc.y, tc.z, tc.w };
    #pragma unroll
    for (int j = 0; j < 4; ++j) {
        float x = xv[j], t = tv[j];
        float e   = __expf(-fabsf(x));
        float l1p = __logf(1.0f + e);
        float bce = l1p + fmaxf(x, 0.f) - t * x;
        float rp  = __fdividef(1.0f, 1.0f + e);
        float p_  = (x >= 0.f) ? rp : e * rp;
        float weit = 1.0f + 5.0f * fabsf(wsv[j] * INV_KK - t);
        r0 += weit * bce;
        r1 += p_ * t * weit;
        r2 += (p_ + t) * weit;
    }
}

// GUARDED = edge strips need row-bound checks; interior strips compile them out.
template<bool GUARDED>
__device__ __forceinline__ void strip_loop(
    const float* pA, const float* pX, int y0,
    bool validA, bool validB, int lane,
    unsigned long long& vA01, unsigned long long& vA23,
    unsigned long long& vB01, unsigned long long& vB23,
    unsigned long long neg1,
    float& r0, float& r1, float& r2)
{
    #pragma unroll 1
    for (int r = 0; r < RPB; r += 2) {
        const int y = y0 + r; (void)y;

        float4 xc1 = __ldcs((const float4*)pX);
        float4 xc2 = __ldcs((const float4*)(pX + IMG_W));
        float4 tc1 = *(const float4*)(pA - 15 * IMG_W + 16);
        float4 tc2 = *(const float4*)(pA - 14 * IMG_W + 16);

        // basis: vs += add1
        if (!GUARDED || (y + KRAD) < IMG_H) {
            if (validA) { ulonglong2 u = *(const ulonglong2*)pA;
                ADDX2(vA01, u.x); ADDX2(vA23, u.y); }
            if (validB) { ulonglong2 u = *(const ulonglong2*)(pA + 128);
                ADDX2(vB01, u.x); ADDX2(vB23, u.y); }
        }
        // delta = add2 - ret1 (independent of basis)
        unsigned long long dA01 = 0ull, dA23 = 0ull, dB01 = 0ull, dB23 = 0ull;
        if (!GUARDED || (y + KRAD + 1) < IMG_H) {
            if (validA) { ulonglong2 u = *(const ulonglong2*)(pA + IMG_W);
                dA01 = u.x; dA23 = u.y; }
            if (validB) { ulonglong2 u = *(const ulonglong2*)(pA + IMG_W + 128);
                dB01 = u.x; dB23 = u.y; }
        }
        if (!GUARDED || (y - KRAD) >= 0) {
            if (validA) { ulonglong2 u = *(const ulonglong2*)(pA - 30 * IMG_W);
                FMANEG(dA01, u.x, neg1); FMANEG(dA23, u.y, neg1); }
            if (validB) { ulonglong2 u = *(const ulonglong2*)(pA - 30 * IMG_W + 128);
                FMANEG(dB01, u.x, neg1); FMANEG(dB23, u.y, neg1); }
        }

        // unpack for the scalar scans
        float a0,a1,a2,a3,b0,b1,b2,b3;
        UNPX2(a0, a1, vA01); UNPX2(a2, a3, vA23);
        UNPX2(b0, b1, vB01); UNPX2(b2, b3, vB23);
        float e0,e1,e2,e3, f0,f1,f2,f3;
        UNPX2(e0, e1, dA01); UNPX2(e2, e3, dA23);
        UNPX2(f0, f1, dB01); UNPX2(f2, f3, dB23);

        // two independent scan chains
        float wsv1[4], wsvd[4];
        window8(a0,a1,a2,a3, b0,b1,b2,b3, lane, wsv1);
        window8(e0,e1,e2,e3, f0,f1,f2,f3, lane, wsvd);
        float wsv2[4] = { wsv1[0]+wsvd[0], wsv1[1]+wsvd[1],
                          wsv1[2]+wsvd[2], wsv1[3]+wsvd[3] };

        accum_pixels(wsv1, xc1, tc1, r0, r1, r2);
        accum_pixels(wsv2, xc2, tc2, r0, r1, r2);

        // fold ret2 into delta; advance basis
        if (!GUARDED || (y - KRAD + 1) >= 0) {
            if (validA) { ulonglong2 u = *(const ulonglong2*)(pA - 29 * IMG_W);
                FMANEG(dA01, u.x, neg1); FMANEG(dA23, u.y, neg1); }
            if (validB) { ulonglong2 u = *(const ulonglong2*)(pA - 29 * IMG_W + 128);
                FMANEG(dB01, u.x, neg1); FMANEG(dB23, u.y, neg1); }
        }
        ADDX2(vA01, dA01); ADDX2(vA23, dA23);
        ADDX2(vB01, dB01); ADDX2(vB23, dB23);

        pA += 2 * IMG_W; pX += 2 * IMG_W;
    }
}

__global__ __launch_bounds__(TPB, 7) void wiou_bce_main(
    const float* __restrict__ X,   // logits
    const float* __restrict__ T,   // targets
    float* __restrict__ out, int nblocks, double inv_count)
{
    __shared__ float red[NW][3];

    const int tid  = threadIdx.x;
    const int lane = tid & 31;
    const int w    = tid >> 5;

    const int bpi = IMG_H / RPB;            // 16 strips per image
    const int n   = blockIdx.x / bpi;
    const int y0  = (blockIdx.x % bpi) * RPB;

    const float* Tn = T + (size_t)n * IMG_H * IMG_W;
    const float* Xn = X + (size_t)n * IMG_H * IMG_W;

    const int colA = w * 128 - 16 + lane * 4;
    const bool validA = !(w == 0 && lane < 4);
    const bool validB = (lane < 8) && !(w == 3 && lane >= 4);

    float nm1 = -1.0f;
    unsigned long long neg1;
    asm("mov.b64 %0, {%1, %2};" : "=l"(neg1) : "f"(nm1), "f"(nm1));

    unsigned long long vA01 = 0ull, vA23 = 0ull, vB01 = 0ull, vB23 = 0ull;

    // ---- prologue: rows [y0-15, y0+14] ----
    {
        int klo = (y0 - KRAD < 0) ? 0 : (y0 - KRAD);
        const float* row = Tn + (ptrdiff_t)klo * IMG_W + colA;
        for (int yy = klo; yy <= y0 + KRAD - 1; ++yy) {
            if (validA) { ulonglong2 u = *(const ulonglong2*)row;
                ADDX2(vA01, u.x); ADDX2(vA23, u.y); }
            if (validB) { ulonglong2 u = *(const ulonglong2*)(row + 128);
                ADDX2(vB01, u.x); ADDX2(vB23, u.y); }
            row += IMG_W;
        }
    }

    float r0 = 0.f, r1 = 0.f, r2 = 0.f;

    const float* pA = Tn + (ptrdiff_t)(y0 + KRAD) * IMG_W + colA;
    const float* pX = Xn + (ptrdiff_t)y0 * IMG_W + (colA + 16);

    // interior strips (y0 in [16, 465]): all row guards constant-true
    if (y0 >= KRAD + 1 && y0 + RPB - 2 + KRAD + 1 < IMG_H) {
        strip_loop<false>(pA, pX, y0, validA, validB, lane,
                          vA01, vA23, vB01, vB23, neg1, r0, r1, r2);
    } else {
        strip_loop<true>(pA, pX, y0, validA, validB, lane,
                         vA01, vA23, vB01, vB23, neg1, r0, r1, r2);
    }

    // ---- block reduction ----
    #pragma unroll
    for (int off = 16; off > 0; off >>= 1) {
        r0 += __shfl_down_sync(FULL, r0, off);
        r1 += __shfl_down_sync(FULL, r1, off);
        r2 += __shfl_down_sync(FULL, r2, off);
    }
    if (lane == 0) { red[w][0] = r0; red[w][1] = r1; red[w][2] = r2; }
    __syncthreads();

    if (tid == 0) {
        float s0 = red[0][0] + red[1][0] + red[2][0] + red[3][0];
        float s1 = red[0][1] + red[1][1] + red[2][1] + red[3][1];
        float s2 = red[0][2] + red[1][2] + red[2][2] + red[3][2];
        atomicAdd(&g_acc[0], (double)s0);
        atomicAdd(&g_acc[1], (double)s1);
        atomicAdd(&g_acc[2], (double)s2);
        __threadfence();
        unsigned int old = atomicAdd(&g_count, 1u);
        if (old == (unsigned int)(nblocks - 1)) {
            __threadfence();
            double d0 = g_acc[0], d1 = g_acc[1], d2 = g_acc[2];
            double wbce = d0 * inv_count;
            double uni  = d2 - d1;
            double wiou = 1.0 - (d1 + 1.0) / (uni + 1.0);
            out[0] = (float)(wbce + wiou);
            g_acc[0] = 0.0; g_acc[1] = 0.0; g_acc[2] = 0.0;
            g_count = 0u;
        }
    }
}

extern "C" void kernel_launch(void* const* d_in, const int* in_sizes, int n_in,
                              void* d_out, int out_size) {
    const float* X = (const float*)d_in[0];
    const float* T = (const float*)d_in[1];
    float* out = (float*)d_out;

    const int n_elem = in_sizes[0];
    const int imgs   = n_elem / (IMG_H * IMG_W);
    const int nb     = imgs * (IMG_H / RPB);

    wiou_bce_main<<<nb, TPB>>>(X, T, out, nb, 1.0 / (double)n_elem);
}